// round 13
// baseline (speedup 1.0000x reference)
#include <cuda_runtime.h>
#include <cuda_fp16.h>
#include <cstdint>

#define N_NODES 100000
#define FDIM 64                 // IN_W == OUT_W == 64
#define E_MAX 2000000

// ---- scratch (no cudaMalloc allowed) ----
// g_pk[i]: bits[40:64) = edge count, bits[0:40) = fixed-point sum(w)*2^32
// (EXCESS degree; self-loop 2.0 added in k_off.)
__device__ unsigned long long g_pk[N_NODES];
__device__ float  g_dinv[N_NODES];
__device__ __half g_h   [(size_t)N_NODES * FDIM];
__device__ int    g_cnt [N_NODES];
__device__ int    g_off [N_NODES];
__device__ int    g_cur [N_NODES];
__device__ int    g_ctr;
__device__ int2   g_pair[E_MAX];    // (src, w-bits)

#define PK_CNT1 (1ULL << 40)
#define PK_DEGMASK ((1ULL << 40) - 1)

// ---------------------------------------------------------------------------
// K0: explicit init every call (no reliance on static zero-init / resets)
__global__ void k_init() {
    int i = blockIdx.x * blockDim.x + threadIdx.x;
    if (i < N_NODES) g_pk[i] = 0ULL;
    if (i == 0) g_ctr = 0;
}

// K1: fused 64-bit RED: cnt++ and deg_excess += w (fixed point)
__global__ void k_deg_acc(const int* __restrict__ ei,
                          const float* __restrict__ w, int E) {
    int e = blockIdx.x * blockDim.x + threadIdx.x;
    if (e < E) {
        int d = ei[E + e];
        unsigned long long add =
            PK_CNT1 + (unsigned long long)(w[e] * 4294967296.0f);
        atomicAdd(&g_pk[d], add);
    }
}

// ---------------------------------------------------------------------------
// K2: unpack (cnt, deg=2+excess); block-local exclusive scan; block base from
// one atomicAdd on g_ctr (ranges disjoint, order irrelevant); fuse dinv.
__global__ void k_off() {
    __shared__ int sm[256];
    __shared__ int base;
    int t = threadIdx.x;
    int i = blockIdx.x * 256 + t;

    int v = 0; float dinv = 0.f;
    if (i < N_NODES) {
        unsigned long long pk = g_pk[i];
        v = (int)(pk >> 40);
        float deg = 2.0f +
            (float)((double)(pk & PK_DEGMASK) * (1.0 / 4294967296.0));
        dinv = rsqrtf(deg);
    }
    sm[t] = v;
    __syncthreads();
    #pragma unroll
    for (int ofs = 1; ofs < 256; ofs <<= 1) {
        int a = (t >= ofs) ? sm[t - ofs] : 0;
        __syncthreads();
        sm[t] += a;
        __syncthreads();
    }
    if (t == 255) base = atomicAdd(&g_ctr, sm[255]);
    __syncthreads();
    if (i < N_NODES) {
        int o = sm[t] - v + base;
        g_off[i]  = o;
        g_cur[i]  = o;
        g_cnt[i]  = v;
        g_dinv[i] = dinv;
    }
}

// ---------------------------------------------------------------------------
// K3: bucket edges by dst, 2 edges/thread for MLP. pair = (src, w-bits).
__global__ void k_bucket(const int* __restrict__ ei,
                         const float* __restrict__ w, int E) {
    int t = blockIdx.x * blockDim.x + threadIdx.x;
    int e0 = t * 2;
    if (e0 >= E) return;

    int  s0 = ei[e0];
    int  d0 = ei[E + e0];
    float w0 = w[e0];
    bool has1 = (e0 + 1 < E);
    int  s1 = 0, d1 = 0; float w1 = 0.f;
    if (has1) { s1 = ei[e0 + 1]; d1 = ei[E + e0 + 1]; w1 = w[e0 + 1]; }

    int p0 = atomicAdd(&g_cur[d0], 1);
    int p1 = has1 ? atomicAdd(&g_cur[d1], 1) : 0;

    g_pair[p0] = make_int2(s0, __float_as_int(w0));
    if (has1) g_pair[p1] = make_int2(s1, __float_as_int(w1));
}

// ---------------------------------------------------------------------------
// K4: register-blocked SGEMM, h only (fp16). No edge-chain dependency;
// runs on a side stream concurrently with K0-K3.
#define BM 96
#define NTHREADS 96
#define XS_STRIDE 68

__global__ __launch_bounds__(NTHREADS)
void k_gemm(const float* __restrict__ x, const float* __restrict__ W) {
    __shared__ float Ws[FDIM * FDIM];        // 16 KB
    __shared__ float xs[BM * XS_STRIDE];     // 25.5 KB

    int tid  = threadIdx.x;
    int row0 = blockIdx.x * BM;
    int nrows = min(BM, N_NODES - row0);

    {
        const float4* W4  = (const float4*)W;
        float4*       Ws4 = (float4*)Ws;
        for (int i = tid; i < FDIM * FDIM / 4; i += NTHREADS) Ws4[i] = W4[i];
    }
    {
        const float4* x4 = (const float4*)(x + (size_t)row0 * FDIM);
        #pragma unroll
        for (int i = 0; i < 16; i++) {
            int idx = tid + i * NTHREADS;
            int row = idx >> 4;
            int kq  = idx & 15;
            float4 v = (row < nrows) ? x4[row * 16 + kq]
                                     : make_float4(0.f, 0.f, 0.f, 0.f);
            int kq_s = kq ^ ((row >> 3) & 3);
            *(float4*)&xs[row * XS_STRIDE + kq_s * 4] = v;
        }
    }
    __syncthreads();

    int ty = tid >> 3;
    int tx = tid & 7;
    int swz = (ty & 3) << 2;

    float acc[8][8];
    #pragma unroll
    for (int i = 0; i < 8; i++)
        #pragma unroll
        for (int j = 0; j < 8; j++) acc[i][j] = 0.f;

    const float* xbase = &xs[(ty * 8) * XS_STRIDE];
    const float* wbase = &Ws[tx * 8];

    #pragma unroll
    for (int k0 = 0; k0 < FDIM; k0 += 4) {
        int kk0 = k0 ^ swz;
        float4 a4[8];
        #pragma unroll
        for (int i = 0; i < 8; i++)
            a4[i] = *(const float4*)&xbase[i * XS_STRIDE + kk0];

        #pragma unroll
        for (int kk = 0; kk < 4; kk++) {
            int k = k0 + kk;
            float4 b0 = *(const float4*)&wbase[k * FDIM];
            float4 b1 = *(const float4*)&wbase[k * FDIM + 4];
            float b[8] = {b0.x, b0.y, b0.z, b0.w, b1.x, b1.y, b1.z, b1.w};
            #pragma unroll
            for (int i = 0; i < 8; i++) {
                float av = (kk == 0) ? a4[i].x : (kk == 1) ? a4[i].y
                         : (kk == 2) ? a4[i].z : a4[i].w;
                #pragma unroll
                for (int j = 0; j < 8; j++)
                    acc[i][j] += av * b[j];
            }
        }
    }

    #pragma unroll
    for (int i = 0; i < 8; i++) {
        int row = row0 + ty * 8 + i;
        if (row >= N_NODES) break;
        size_t base = (size_t)row * FDIM + tx * 8;
        __half2 hh[4];
        hh[0] = __floats2half2_rn(acc[i][0], acc[i][1]);
        hh[1] = __floats2half2_rn(acc[i][2], acc[i][3]);
        hh[2] = __floats2half2_rn(acc[i][4], acc[i][5]);
        hh[3] = __floats2half2_rn(acc[i][6], acc[i][7]);
        *(uint4*)&g_h[base] = *(uint4*)hh;
    }
}

// ---------------------------------------------------------------------------
// K5: gather, unrolled x8 for MLP. Sole writer of out:
//   out[d] = dinv_d * ( sum_e dinv_s*w*h[s] + 2*dinv_d*h[d] ) + bias
__device__ __forceinline__ void acc_half4(float4& acc, uint2 u, float c) {
    float2 f0 = __half22float2(*(__half2*)&u.x);
    float2 f1 = __half22float2(*(__half2*)&u.y);
    acc.x += c * f0.x; acc.y += c * f0.y;
    acc.z += c * f1.x; acc.w += c * f1.y;
}

__global__ void k_gather(const float* __restrict__ bias,
                         float* __restrict__ out) {
    int t = blockIdx.x * blockDim.x + threadIdx.x;
    int node = t >> 4;
    int l    = t & 15;
    if (node >= N_NODES) return;

    int start = g_off[node];
    int n     = g_cnt[node];
    const int2* pr = &g_pair[start];

    float dd = g_dinv[node];
    float4 acc = make_float4(0.f, 0.f, 0.f, 0.f);

    // self loop: + 2*dd * h[node]
    {
        uint2 hv = ((const uint2*)(g_h + (size_t)node * FDIM))[l];
        acc_half4(acc, hv, 2.0f * dd);
    }

    int j = 0;
    for (; j + 8 <= n; j += 8) {
        int2  p[8];
        uint2 v[8];
        float c[8];
        #pragma unroll
        for (int q = 0; q < 8; q++) p[q] = pr[j + q];
        #pragma unroll
        for (int q = 0; q < 8; q++)
            v[q] = ((const uint2*)(g_h + (size_t)p[q].x * FDIM))[l];
        #pragma unroll
        for (int q = 0; q < 8; q++)
            c[q] = g_dinv[p[q].x] * __int_as_float(p[q].y);
        #pragma unroll
        for (int q = 0; q < 8; q++) acc_half4(acc, v[q], c[q]);
    }
    for (; j + 4 <= n; j += 4) {
        int2 p0 = pr[j],     p1 = pr[j + 1];
        int2 p2 = pr[j + 2], p3 = pr[j + 3];
        uint2 v0 = ((const uint2*)(g_h + (size_t)p0.x * FDIM))[l];
        uint2 v1 = ((const uint2*)(g_h + (size_t)p1.x * FDIM))[l];
        uint2 v2 = ((const uint2*)(g_h + (size_t)p2.x * FDIM))[l];
        uint2 v3 = ((const uint2*)(g_h + (size_t)p3.x * FDIM))[l];
        acc_half4(acc, v0, g_dinv[p0.x] * __int_as_float(p0.y));
        acc_half4(acc, v1, g_dinv[p1.x] * __int_as_float(p1.y));
        acc_half4(acc, v2, g_dinv[p2.x] * __int_as_float(p2.y));
        acc_half4(acc, v3, g_dinv[p3.x] * __int_as_float(p3.y));
    }
    for (; j < n; j++) {
        int2 p = pr[j];
        uint2 v = ((const uint2*)(g_h + (size_t)p.x * FDIM))[l];
        acc_half4(acc, v, g_dinv[p.x] * __int_as_float(p.y));
    }

    float4 bv = ((const float4*)bias)[l];
    float4 o = make_float4(dd * acc.x + bv.x, dd * acc.y + bv.y,
                           dd * acc.z + bv.z, dd * acc.w + bv.w);
    ((float4*)(out + (size_t)node * FDIM))[l] = o;
}

// ---------------------------------------------------------------------------
extern "C" void kernel_launch(void* const* d_in, const int* in_sizes, int n_in,
                              void* d_out, int out_size) {
    const float* x   = (const float*)d_in[0];       // [N, 64]
    const float* ew  = (const float*)d_in[1];       // [E]
    const float* W   = (const float*)d_in[2];       // [64, 64]
    const float* b   = (const float*)d_in[3];       // [64]
    const int*   ei  = (const int*)d_in[4];         // [2, E] int32
    // d_in[5] = batch, unused

    int E = in_sizes[1];
    float* out = (float*)d_out;

    // Side stream + events, created once (no device memory involved).
    static cudaStream_t s2 = nullptr;
    static cudaEvent_t  ev_fork = nullptr, ev_join = nullptr;
    if (s2 == nullptr) {
        cudaStreamCreateWithFlags(&s2, cudaStreamNonBlocking);
        cudaEventCreateWithFlags(&ev_fork, cudaEventDisableTiming);
        cudaEventCreateWithFlags(&ev_join, cudaEventDisableTiming);
    }

    // Fork: GEMM (FFMA-bound) on s2 || edge chain (L2-bound) on main stream.
    cudaEventRecord(ev_fork, 0);
    cudaStreamWaitEvent(s2, ev_fork, 0);
    k_gemm<<<(N_NODES + BM - 1) / BM, NTHREADS, 0, s2>>>(x, W);
    cudaEventRecord(ev_join, s2);

    k_init   <<<(N_NODES + 255) / 256, 256>>>();
    k_deg_acc<<<(E + 255) / 256, 256>>>(ei, ew, E);
    k_off    <<<(N_NODES + 255) / 256, 256>>>();
    int nb = (E / 2 + 255) / 256;
    k_bucket <<<nb, 256>>>(ei, ew, E);

    // Join, then gather (sole writer of out).
    cudaStreamWaitEvent(0, ev_join, 0);
    long long gt = (long long)N_NODES * 16;
    k_gather<<<(unsigned)((gt + 255) / 256), 256>>>(b, out);
}